// round 16
// baseline (speedup 1.0000x reference)
#include <cuda_runtime.h>
#include <cstdint>

// Problem constants: N=100000, E=1600000, D=H=128, C=40
#define NMAX 100096
#define EMAX 1600000
#define SCAN_CH 1024
#define NBMAX 128

// ---------------- scratch (device globals; zero-initialized at load) --------
__device__ int   g_cnt[NMAX];          // invariant: zero at entry of each launch
__device__ int   g_row[NMAX + 1];
__device__ int   g_cur[NMAX];
__device__ int   g_col[EMAX];
__device__ float g_dinv[NMAX];
__device__ int   g_bsum[NBMAX];
__device__ float g_h0[(size_t)NMAX * 128];
__device__ float g_h1[(size_t)NMAX * 128];
__device__ float g_h2[(size_t)NMAX * 40];

// ---------------- packed f32x2 helpers ---------------------------------------
#define FMA2(d, a, b, c) \
    asm("fma.rn.f32x2 %0, %1, %2, %3;" : "=l"(d) : "l"(a), "l"(b), "l"(c))
#define ADD2(d, a, b) \
    asm("add.rn.f32x2 %0, %1, %2;" : "=l"(d) : "l"(a), "l"(b))
#define PACKDUP(d, s) \
    asm("mov.b64 %0, {%1, %1};" : "=l"(d) : "r"(s))
#define CP_ASYNC16(dst, src) \
    asm volatile("cp.async.ca.shared.global [%0], [%1], 16;" :: "r"(dst), "l"(src))
#define CP_ASYNC16P(dst, src, sz) \
    asm volatile("cp.async.ca.shared.global [%0], [%1], 16, %2;" :: "r"(dst), "l"(src), "r"(sz))
#define CP_COMMIT() asm volatile("cp.async.commit_group;" ::: "memory")
#define CP_WAIT1()  asm volatile("cp.async.wait_group 1;" ::: "memory")
#define CP_WAIT0()  asm volatile("cp.async.wait_group 0;" ::: "memory")

union U64F2 { unsigned long long u; float2 f; };
union F4U2 { float4 f; unsigned long long u[2]; };

// ---------------- CSR build (4 kernels) --------------------------------------
__global__ void k_count(const int* __restrict__ dst, int E) {
    int e = blockIdx.x * blockDim.x + threadIdx.x;
    if (e < E) atomicAdd(&g_cnt[dst[e]], 1);
}
__global__ void k_scan1(int n) {
    __shared__ int s[SCAN_CH];
    int tid = threadIdx.x;
    int i = blockIdx.x * SCAN_CH + tid;
    int v = (i < n) ? g_cnt[i] : 0;
    s[tid] = v;
    __syncthreads();
    #pragma unroll
    for (int off = 1; off < SCAN_CH; off <<= 1) {
        int t = (tid >= off) ? s[tid - off] : 0;
        __syncthreads();
        s[tid] += t;
        __syncthreads();
    }
    if (i < n) g_row[i] = s[tid] - v;
    if (tid == SCAN_CH - 1) g_bsum[blockIdx.x] = s[tid];
}
// Fused: per-block redundant scan of chunk sums + apply + dinv + re-zero g_cnt
__global__ void k_scan23(int n, int E, int nb) {
    __shared__ int s[NBMAX];
    int tid = threadIdx.x;
    if (tid < NBMAX) {
        int v = (tid < nb) ? g_bsum[tid] : 0;
        s[tid] = v;
    }
    __syncthreads();
    #pragma unroll
    for (int off = 1; off < NBMAX; off <<= 1) {
        int t = 0;
        if (tid < NBMAX && tid >= off) t = s[tid - off];
        __syncthreads();
        if (tid < NBMAX) s[tid] += t;
        __syncthreads();
    }
    int i = blockIdx.x * blockDim.x + tid;
    if (i < n) {
        int c = g_cnt[i];
        int chunk = i >> 10;
        int base = (chunk > 0) ? s[chunk - 1] : 0;    // exclusive prefix
        int r = g_row[i] + base;
        g_row[i] = r;
        g_cur[i] = r;
        g_dinv[i] = rsqrtf((float)(c + 1));           // +1 self loop
        g_cnt[i] = 0;                                 // restore invariant
    }
    if (i == 0) g_row[n] = E;
}
__global__ void k_scatter(const int* __restrict__ src, const int* __restrict__ dst, int E) {
    int e = blockIdx.x * blockDim.x + threadIdx.x;
    if (e < E) {
        int d = dst[e];
        int p = atomicAdd(&g_cur[d], 1);
        g_col[p] = src[e];
    }
}

// ---------------- GEMM: [N,128] @ [128,128], f32x2 + cp.async pipeline ------
// Tile 64x128, 256 threads, microtile 4x8 (16x16 thread grid) -> ~85 regs,
// 3 CTAs/SM = 24 warps (6/SMSP) for LDS-latency hiding. BK=32 x 4 chunks,
// double buffered. Epilogue scales rows by g_dinv (dinv pre-multiplication).
#define GX_PAD 36
#define GSM_X  (2 * 64 * GX_PAD)                 // floats
#define GSM_TOTAL ((GSM_X + 2 * 32 * 128) * 4)   // bytes = 51200

__device__ __forceinline__ void g128_load_chunk(float* Xs, float* Ws,
                                                const float* __restrict__ X,
                                                const float* __restrict__ W,
                                                int row0, int N, int tid, int kk, int b) {
    // X chunk: 64 rows x 32 cols = 512 float4 -> 2 per thread
    #pragma unroll
    for (int i = 0; i < 2; i++) {
        int idx = tid + 256 * i;
        int r = idx >> 3, c4 = (idx & 7) << 2;
        uint32_t d = (uint32_t)__cvta_generic_to_shared(&Xs[(b * 64 + r) * GX_PAD + c4]);
        const float* s = X + (size_t)(row0 + r) * 128 + kk * 32 + c4;
        int sz = (row0 + r < N) ? 16 : 0;
        CP_ASYNC16P(d, s, sz);
    }
    // W chunk: 32 rows x 128 cols = 1024 float4 -> 4 per thread
    #pragma unroll
    for (int i = 0; i < 4; i++) {
        int idx = tid + 256 * i;
        int k = idx >> 5, c4 = (idx & 31) << 2;
        uint32_t d = (uint32_t)__cvta_generic_to_shared(&Ws[(b * 32 + k) * 128 + c4]);
        const float* s = W + (size_t)(kk * 32 + k) * 128 + c4;
        CP_ASYNC16(d, s);
    }
}

__global__ void __launch_bounds__(256, 3) k_gemm128(const float* __restrict__ Xext, int inSel,
                                                    const float* __restrict__ W, int outSel, int N) {
    extern __shared__ float sm[];
    float* Xs = sm;                 // [2][64][36]
    float* Ws = sm + GSM_X;         // [2][32][128]
    const float* X = Xext ? Xext : (inSel == 0 ? g_h0 : g_h1);
    float* Y = (outSel == 0) ? g_h0 : g_h1;
    int tid = threadIdx.x;
    int row0 = blockIdx.x * 64;
    int rg = tid >> 4, cg = tid & 15;      // 16 row-groups (4 rows) x 16 col-groups (8 cols)

    unsigned long long acc[4][4];
    #pragma unroll
    for (int i = 0; i < 4; i++)
        #pragma unroll
        for (int j = 0; j < 4; j++) acc[i][j] = 0ull;

    g128_load_chunk(Xs, Ws, X, W, row0, N, tid, 0, 0); CP_COMMIT();
    g128_load_chunk(Xs, Ws, X, W, row0, N, tid, 1, 1); CP_COMMIT();

    #pragma unroll
    for (int kk = 0; kk < 4; kk++) {
        int b = kk & 1;
        if (kk < 3) { CP_WAIT1(); } else { CP_WAIT0(); }
        __syncthreads();
        #pragma unroll 4
        for (int k = 0; k < 32; k++) {
            unsigned long long ap[4], bp[4];
            #pragma unroll
            for (int i = 0; i < 4; i++) {
                unsigned int av = __float_as_uint(Xs[(b * 64 + rg * 4 + i) * GX_PAD + k]);
                PACKDUP(ap[i], av);
            }
            F4U2 b0, b1;
            b0.f = *(const float4*)&Ws[(b * 32 + k) * 128 + cg * 8];
            b1.f = *(const float4*)&Ws[(b * 32 + k) * 128 + cg * 8 + 4];
            bp[0] = b0.u[0]; bp[1] = b0.u[1]; bp[2] = b1.u[0]; bp[3] = b1.u[1];
            #pragma unroll
            for (int i = 0; i < 4; i++)
                #pragma unroll
                for (int j = 0; j < 4; j++)
                    FMA2(acc[i][j], ap[i], bp[j], acc[i][j]);
        }
        if (kk + 2 < 4) {
            __syncthreads();          // buffer b fully consumed before refill
            g128_load_chunk(Xs, Ws, X, W, row0, N, tid, kk + 2, b);
            CP_COMMIT();
        }
    }

    #pragma unroll
    for (int i = 0; i < 4; i++) {
        int gr = row0 + rg * 4 + i;
        if (gr < N) {
            float dv = g_dinv[gr];
            #pragma unroll
            for (int j = 0; j < 2; j++) {
                U64F2 c0, c1;
                c0.u = acc[i][2 * j]; c1.u = acc[i][2 * j + 1];
                *(float4*)(Y + (size_t)gr * 128 + cg * 8 + 4 * j) =
                    make_float4(dv * c0.f.x, dv * c0.f.y, dv * c1.f.x, dv * c1.f.y);
            }
        }
    }
}

// ---------------- GEMM: [N,128] @ [128,40] (in g_h1, out g_h2), FFMA --------
// Epilogue scales by g_dinv[row].
__global__ void __launch_bounds__(128) k_gemm40(const float* __restrict__ W, int N) {
    __shared__ float Xs[128][33];
    __shared__ float Ws[32][40];
    int tid = threadIdx.x;
    int row0 = blockIdx.x * 128;
    int rg = tid >> 3, cg = tid & 7;
    float acc[8][5];
    #pragma unroll
    for (int i = 0; i < 8; i++)
        #pragma unroll
        for (int j = 0; j < 5; j++) acc[i][j] = 0.f;

    for (int k0 = 0; k0 < 128; k0 += 32) {
        #pragma unroll
        for (int i = 0; i < 8; i++) {
            int idx = tid + 128 * i;
            int r = idx >> 3, c4 = (idx & 7) << 2;
            int gr = row0 + r;
            float4 v = make_float4(0.f, 0.f, 0.f, 0.f);
            if (gr < N) v = *(const float4*)(g_h1 + (size_t)gr * 128 + k0 + c4);
            Xs[r][c4 + 0] = v.x; Xs[r][c4 + 1] = v.y;
            Xs[r][c4 + 2] = v.z; Xs[r][c4 + 3] = v.w;
        }
        #pragma unroll
        for (int i = 0; i < 10; i++) {
            int idx = tid + 128 * i;
            int r = idx / 40, c = idx % 40;
            Ws[r][c] = W[(size_t)(k0 + r) * 40 + c];
        }
        __syncthreads();
        #pragma unroll 8
        for (int k = 0; k < 32; k++) {
            float a[8], b[5];
            #pragma unroll
            for (int i = 0; i < 8; i++) a[i] = Xs[rg * 8 + i][k];
            #pragma unroll
            for (int j = 0; j < 5; j++) b[j] = Ws[k][cg * 5 + j];
            #pragma unroll
            for (int i = 0; i < 8; i++)
                #pragma unroll
                for (int j = 0; j < 5; j++) acc[i][j] = fmaf(a[i], b[j], acc[i][j]);
        }
        __syncthreads();
    }
    #pragma unroll
    for (int i = 0; i < 8; i++) {
        int gr = row0 + rg * 8 + i;
        if (gr < N) {
            float dv = g_dinv[gr];
            #pragma unroll
            for (int j = 0; j < 5; j++)
                g_h2[(size_t)gr * 40 + cg * 5 + j] = dv * acc[i][j];
        }
    }
}

// ---------------- Aggregation (pull-CSR), 128 features, 1 warp / node -------
// Inputs dinv-premultiplied; inner loop = gather + packed f32x2 adds.
__global__ void __launch_bounds__(256) k_agg128(int inSel, int outSel,
                                                const float* __restrict__ bias, int relu, int n) {
    const float* __restrict__ t = (inSel == 0) ? g_h0 : g_h1;
    float* o = (outSel == 0) ? g_h0 : g_h1;
    int warp = (blockIdx.x * 256 + threadIdx.x) >> 5;
    int lane = threadIdx.x & 31;
    if (warp >= n) return;
    int v = warp;
    F4U2 a0;
    a0.f = *(const float4*)(t + (size_t)v * 128 + lane * 4);   // self loop (z'[v])
    unsigned long long acc0 = a0.u[0], acc1 = a0.u[1];
    int rb = g_row[v], re = g_row[v + 1];
    for (int s0 = rb; s0 < re; s0 += 32) {
        int idx = s0 + lane;
        int u = 0;
        if (idx < re) u = g_col[idx];
        int cnt = min(32, re - s0);
        int j = 0;
        for (; j + 8 <= cnt; j += 8) {
            int uu[8]; F4U2 rr[8];
            #pragma unroll
            for (int q = 0; q < 8; q++)
                uu[q] = __shfl_sync(0xffffffffu, u, j + q);
            #pragma unroll
            for (int q = 0; q < 8; q++)
                rr[q].f = *(const float4*)(t + (size_t)uu[q] * 128 + lane * 4);
            #pragma unroll
            for (int q = 0; q < 8; q++) {
                ADD2(acc0, acc0, rr[q].u[0]);
                ADD2(acc1, acc1, rr[q].u[1]);
            }
        }
        for (; j < cnt; j++) {
            int uj = __shfl_sync(0xffffffffu, u, j);
            F4U2 r;
            r.f = *(const float4*)(t + (size_t)uj * 128 + lane * 4);
            ADD2(acc0, acc0, r.u[0]);
            ADD2(acc1, acc1, r.u[1]);
        }
    }
    float dv = g_dinv[v];
    float4 bv = *(const float4*)(bias + lane * 4);
    U64F2 c0, c1;
    c0.u = acc0; c1.u = acc1;
    float4 out;
    out.x = fmaf(dv, c0.f.x, bv.x);
    out.y = fmaf(dv, c0.f.y, bv.y);
    out.z = fmaf(dv, c1.f.x, bv.z);
    out.w = fmaf(dv, c1.f.y, bv.w);
    if (relu) {
        out.x = fmaxf(out.x, 0.f); out.y = fmaxf(out.y, 0.f);
        out.z = fmaxf(out.z, 0.f); out.w = fmaxf(out.w, 0.f);
    }
    *(float4*)(o + (size_t)v * 128 + lane * 4) = out;
}

// ---------------- Aggregation, 40 features (in g_h2, out ext) ---------------
__global__ void __launch_bounds__(256) k_agg40(float* __restrict__ O,
                                               const float* __restrict__ bias, int n) {
    int warp = (blockIdx.x * 256 + threadIdx.x) >> 5;
    int lane = threadIdx.x & 31;
    if (warp >= n) return;
    int v = warp;
    bool act = lane < 10;
    unsigned long long acc0 = 0ull, acc1 = 0ull;
    if (act) {
        F4U2 a0;
        a0.f = *(const float4*)(g_h2 + (size_t)v * 40 + lane * 4);
        acc0 = a0.u[0]; acc1 = a0.u[1];
    }
    int rb = g_row[v], re = g_row[v + 1];
    for (int s0 = rb; s0 < re; s0 += 32) {
        int idx = s0 + lane;
        int u = 0;
        if (idx < re) u = g_col[idx];
        int cnt = min(32, re - s0);
        int j = 0;
        for (; j + 4 <= cnt; j += 4) {
            int uu[4];
            #pragma unroll
            for (int q = 0; q < 4; q++)
                uu[q] = __shfl_sync(0xffffffffu, u, j + q);
            if (act) {
                F4U2 rr[4];
                #pragma unroll
                for (int q = 0; q < 4; q++)
                    rr[q].f = *(const float4*)(g_h2 + (size_t)uu[q] * 40 + lane * 4);
                #pragma unroll
                for (int q = 0; q < 4; q++) {
                    ADD2(acc0, acc0, rr[q].u[0]);
                    ADD2(acc1, acc1, rr[q].u[1]);
                }
            }
        }
        for (; j < cnt; j++) {
            int uj = __shfl_sync(0xffffffffu, u, j);
            if (act) {
                F4U2 r;
                r.f = *(const float4*)(g_h2 + (size_t)uj * 40 + lane * 4);
                ADD2(acc0, acc0, r.u[0]);
                ADD2(acc1, acc1, r.u[1]);
            }
        }
    }
    if (act) {
        float dv = g_dinv[v];
        float4 bv = *(const float4*)(bias + lane * 4);
        U64F2 c0, c1;
        c0.u = acc0; c1.u = acc1;
        float4 out;
        out.x = fmaf(dv, c0.f.x, bv.x);
        out.y = fmaf(dv, c0.f.y, bv.y);
        out.z = fmaf(dv, c1.f.x, bv.z);
        out.w = fmaf(dv, c1.f.y, bv.w);
        *(float4*)(O + (size_t)v * 40 + lane * 4) = out;
    }
}

// ---------------- launch -----------------------------------------------------
extern "C" void kernel_launch(void* const* d_in, const int* in_sizes, int n_in,
                              void* d_out, int out_size) {
    const float* x  = (const float*)d_in[0];
    const int*   ei = (const int*)d_in[1];
    const float* W0 = (const float*)d_in[2];
    const float* b0 = (const float*)d_in[3];
    const float* W1 = (const float*)d_in[4];
    const float* b1 = (const float*)d_in[5];
    const float* W2 = (const float*)d_in[6];
    const float* b2 = (const float*)d_in[7];
    float* out = (float*)d_out;

    int N = in_sizes[0] / 128;
    int E = in_sizes[1] / 2;
    const int* src = ei;
    const int* dst = ei + E;

    static bool inited = false;
    if (!inited) {
        inited = true;
        cudaFuncSetAttribute(k_gemm128, cudaFuncAttributeMaxDynamicSharedMemorySize, GSM_TOTAL);
    }

    int gb64 = (N + 63) / 64;
    int gb  = (N + 127) / 128;
    int ab  = (N + 7) / 8;
    int nb  = (N + SCAN_CH - 1) / SCAN_CH;

    // CSR: g_cnt is zero on entry (module init + re-zeroed by k_scan23 each call).
    // gemm epilogues read g_dinv, so gemm0 must follow k_scan23 (it does).
    k_count  <<<(E + 255) / 256, 256>>>(dst, E);            // #1
    k_scan1  <<<nb, SCAN_CH>>>(N);                          // #2
    k_scan23 <<<(N + 255) / 256, 256>>>(N, E, nb);          // #3
    k_gemm128<<<gb64, 256, GSM_TOTAL>>>(x, -1, W0, 0, N);   // #4 (profiled slot)
    k_scatter<<<(E + 255) / 256, 256>>>(src, dst, E);       // #5

    // layer 0: agg(h0) + b0, relu -> h1
    k_agg128 <<<ab, 256>>>(0, 1, b0, 1, N);
    // layer 1: h1 @ W1 -> h0 (dinv-scaled) ; agg(h0) + b1, relu -> h1
    k_gemm128<<<gb64, 256, GSM_TOTAL>>>(nullptr, 1, W1, 0, N);
    k_agg128 <<<ab, 256>>>(0, 1, b1, 1, N);
    // layer 2: h1 @ W2 -> h2 (dinv-scaled) ; agg(h2) + b2 -> out
    k_gemm40 <<<gb, 128>>>(W2, N);
    k_agg40  <<<ab, 256>>>(out, b2, N);
}

// round 17
// speedup vs baseline: 1.2284x; 1.2284x over previous
#include <cuda_runtime.h>
#include <cstdint>

// Problem constants: N=100000, E=1600000, D=H=128, C=40
#define NMAX 100096
#define EMAX 1600000
#define SCAN_CH 1024
#define NBMAX 128

// ---------------- scratch (device globals; zero-initialized at load) --------
__device__ int   g_cnt[NMAX];          // invariant: zero at entry of each launch
__device__ int   g_row[NMAX + 1];
__device__ int   g_cur[NMAX];
__device__ int   g_col[EMAX];
__device__ float g_dinv[NMAX];
__device__ int   g_bsum[NBMAX];
__device__ float g_h0[(size_t)NMAX * 128];
__device__ float g_h1[(size_t)NMAX * 128];
__device__ float g_h2[(size_t)NMAX * 40];

// ---------------- packed f32x2 helpers ---------------------------------------
#define FMA2(d, a, b, c) \
    asm("fma.rn.f32x2 %0, %1, %2, %3;" : "=l"(d) : "l"(a), "l"(b), "l"(c))
#define ADD2(d, a, b) \
    asm("add.rn.f32x2 %0, %1, %2;" : "=l"(d) : "l"(a), "l"(b))
#define PACKDUP(d, s) \
    asm("mov.b64 %0, {%1, %1};" : "=l"(d) : "r"(s))
#define CP_ASYNC16(dst, src) \
    asm volatile("cp.async.ca.shared.global [%0], [%1], 16;" :: "r"(dst), "l"(src))
#define CP_ASYNC16P(dst, src, sz) \
    asm volatile("cp.async.ca.shared.global [%0], [%1], 16, %2;" :: "r"(dst), "l"(src), "r"(sz))
#define CP_COMMIT() asm volatile("cp.async.commit_group;" ::: "memory")
#define CP_WAIT1()  asm volatile("cp.async.wait_group 1;" ::: "memory")
#define CP_WAIT0()  asm volatile("cp.async.wait_group 0;" ::: "memory")

union U64F2 { unsigned long long u; float2 f; };
union F4U2 { float4 f; unsigned long long u[2]; };

// ---------------- CSR build (4 kernels) --------------------------------------
__global__ void k_count(const int* __restrict__ dst, int E) {
    int e = blockIdx.x * blockDim.x + threadIdx.x;
    if (e < E) atomicAdd(&g_cnt[dst[e]], 1);
}
__global__ void k_scan1(int n) {
    __shared__ int s[SCAN_CH];
    int tid = threadIdx.x;
    int i = blockIdx.x * SCAN_CH + tid;
    int v = (i < n) ? g_cnt[i] : 0;
    s[tid] = v;
    __syncthreads();
    #pragma unroll
    for (int off = 1; off < SCAN_CH; off <<= 1) {
        int t = (tid >= off) ? s[tid - off] : 0;
        __syncthreads();
        s[tid] += t;
        __syncthreads();
    }
    if (i < n) g_row[i] = s[tid] - v;
    if (tid == SCAN_CH - 1) g_bsum[blockIdx.x] = s[tid];
}
// Fused: per-block redundant scan of chunk sums + apply + dinv + re-zero g_cnt
__global__ void k_scan23(int n, int E, int nb) {
    __shared__ int s[NBMAX];
    int tid = threadIdx.x;
    if (tid < NBMAX) {
        int v = (tid < nb) ? g_bsum[tid] : 0;
        s[tid] = v;
    }
    __syncthreads();
    #pragma unroll
    for (int off = 1; off < NBMAX; off <<= 1) {
        int t = 0;
        if (tid < NBMAX && tid >= off) t = s[tid - off];
        __syncthreads();
        if (tid < NBMAX) s[tid] += t;
        __syncthreads();
    }
    int i = blockIdx.x * blockDim.x + tid;
    if (i < n) {
        int c = g_cnt[i];
        int chunk = i >> 10;
        int base = (chunk > 0) ? s[chunk - 1] : 0;    // exclusive prefix
        int r = g_row[i] + base;
        g_row[i] = r;
        g_cur[i] = r;
        g_dinv[i] = rsqrtf((float)(c + 1));           // +1 self loop
        g_cnt[i] = 0;                                 // restore invariant
    }
    if (i == 0) g_row[n] = E;
}
__global__ void k_scatter(const int* __restrict__ src, const int* __restrict__ dst, int E) {
    int e = blockIdx.x * blockDim.x + threadIdx.x;
    if (e < E) {
        int d = dst[e];
        int p = atomicAdd(&g_cur[d], 1);
        g_col[p] = src[e];
    }
}

// ---------------- GEMM: [N,128] @ [128,128], f32x2 + cp.async pipeline ------
// Tile 64x128, 128 threads, 8x8 microtile, (128,3)/~166 regs — measured-best
// config (74us). Epilogue scales rows by g_dinv (dinv pre-multiplication).
#define GX_PAD 36
#define GSM_X  (2 * 64 * GX_PAD)                 // floats
#define GSM_TOTAL ((GSM_X + 2 * 32 * 128) * 4)   // bytes = 51200

__device__ __forceinline__ void g128_load_chunk(float* Xs, float* Ws,
                                                const float* __restrict__ X,
                                                const float* __restrict__ W,
                                                int row0, int N, int tid, int kk, int b) {
    #pragma unroll
    for (int i = 0; i < 4; i++) {
        int idx = tid + 128 * i;
        int r = idx >> 3, c4 = (idx & 7) << 2;
        uint32_t d = (uint32_t)__cvta_generic_to_shared(&Xs[(b * 64 + r) * GX_PAD + c4]);
        const float* s = X + (size_t)(row0 + r) * 128 + kk * 32 + c4;
        int sz = (row0 + r < N) ? 16 : 0;
        CP_ASYNC16P(d, s, sz);
    }
    #pragma unroll
    for (int i = 0; i < 8; i++) {
        int idx = tid + 128 * i;
        int k = idx >> 5, c4 = (idx & 31) << 2;
        uint32_t d = (uint32_t)__cvta_generic_to_shared(&Ws[(b * 32 + k) * 128 + c4]);
        const float* s = W + (size_t)(kk * 32 + k) * 128 + c4;
        CP_ASYNC16(d, s);
    }
}

__global__ void __launch_bounds__(128, 3) k_gemm128(const float* __restrict__ Xext, int inSel,
                                                    const float* __restrict__ W, int outSel, int N) {
    extern __shared__ float sm[];
    float* Xs = sm;                 // [2][64][36]
    float* Ws = sm + GSM_X;         // [2][32][128]
    const float* X = Xext ? Xext : (inSel == 0 ? g_h0 : g_h1);
    float* Y = (outSel == 0) ? g_h0 : g_h1;
    int tid = threadIdx.x;
    int row0 = blockIdx.x * 64;
    int rg = tid >> 4, cg = tid & 15;

    unsigned long long acc[8][4];
    #pragma unroll
    for (int i = 0; i < 8; i++)
        #pragma unroll
        for (int j = 0; j < 4; j++) acc[i][j] = 0ull;

    g128_load_chunk(Xs, Ws, X, W, row0, N, tid, 0, 0); CP_COMMIT();
    g128_load_chunk(Xs, Ws, X, W, row0, N, tid, 1, 1); CP_COMMIT();

    #pragma unroll
    for (int kk = 0; kk < 4; kk++) {
        int b = kk & 1;
        if (kk < 3) { CP_WAIT1(); } else { CP_WAIT0(); }
        __syncthreads();
        #pragma unroll 4
        for (int k = 0; k < 32; k++) {
            unsigned long long ap[8], bp[4];
            #pragma unroll
            for (int i = 0; i < 8; i++) {
                unsigned int av = __float_as_uint(Xs[(b * 64 + rg * 8 + i) * GX_PAD + k]);
                PACKDUP(ap[i], av);
            }
            F4U2 b0, b1;
            b0.f = *(const float4*)&Ws[(b * 32 + k) * 128 + cg * 8];
            b1.f = *(const float4*)&Ws[(b * 32 + k) * 128 + cg * 8 + 4];
            bp[0] = b0.u[0]; bp[1] = b0.u[1]; bp[2] = b1.u[0]; bp[3] = b1.u[1];
            #pragma unroll
            for (int i = 0; i < 8; i++)
                #pragma unroll
                for (int j = 0; j < 4; j++)
                    FMA2(acc[i][j], ap[i], bp[j], acc[i][j]);
        }
        if (kk + 2 < 4) {
            __syncthreads();          // buffer b fully consumed before refill
            g128_load_chunk(Xs, Ws, X, W, row0, N, tid, kk + 2, b);
            CP_COMMIT();
        }
    }

    #pragma unroll
    for (int i = 0; i < 8; i++) {
        int gr = row0 + rg * 8 + i;
        if (gr < N) {
            float dv = g_dinv[gr];
            #pragma unroll
            for (int j = 0; j < 2; j++) {
                U64F2 c0, c1;
                c0.u = acc[i][2 * j]; c1.u = acc[i][2 * j + 1];
                *(float4*)(Y + (size_t)gr * 128 + cg * 8 + 4 * j) =
                    make_float4(dv * c0.f.x, dv * c0.f.y, dv * c1.f.x, dv * c1.f.y);
            }
        }
    }
}

// ---------------- GEMM: [N,128] @ [128,40] (in g_h1, out g_h2), FFMA --------
// Epilogue scales by g_dinv[row].
__global__ void __launch_bounds__(128) k_gemm40(const float* __restrict__ W, int N) {
    __shared__ float Xs[128][33];
    __shared__ float Ws[32][40];
    int tid = threadIdx.x;
    int row0 = blockIdx.x * 128;
    int rg = tid >> 3, cg = tid & 7;
    float acc[8][5];
    #pragma unroll
    for (int i = 0; i < 8; i++)
        #pragma unroll
        for (int j = 0; j < 5; j++) acc[i][j] = 0.f;

    for (int k0 = 0; k0 < 128; k0 += 32) {
        #pragma unroll
        for (int i = 0; i < 8; i++) {
            int idx = tid + 128 * i;
            int r = idx >> 3, c4 = (idx & 7) << 2;
            int gr = row0 + r;
            float4 v = make_float4(0.f, 0.f, 0.f, 0.f);
            if (gr < N) v = *(const float4*)(g_h1 + (size_t)gr * 128 + k0 + c4);
            Xs[r][c4 + 0] = v.x; Xs[r][c4 + 1] = v.y;
            Xs[r][c4 + 2] = v.z; Xs[r][c4 + 3] = v.w;
        }
        #pragma unroll
        for (int i = 0; i < 10; i++) {
            int idx = tid + 128 * i;
            int r = idx / 40, c = idx % 40;
            Ws[r][c] = W[(size_t)(k0 + r) * 40 + c];
        }
        __syncthreads();
        #pragma unroll 8
        for (int k = 0; k < 32; k++) {
            float a[8], b[5];
            #pragma unroll
            for (int i = 0; i < 8; i++) a[i] = Xs[rg * 8 + i][k];
            #pragma unroll
            for (int j = 0; j < 5; j++) b[j] = Ws[k][cg * 5 + j];
            #pragma unroll
            for (int i = 0; i < 8; i++)
                #pragma unroll
                for (int j = 0; j < 5; j++) acc[i][j] = fmaf(a[i], b[j], acc[i][j]);
        }
        __syncthreads();
    }
    #pragma unroll
    for (int i = 0; i < 8; i++) {
        int gr = row0 + rg * 8 + i;
        if (gr < N) {
            float dv = g_dinv[gr];
            #pragma unroll
            for (int j = 0; j < 5; j++)
                g_h2[(size_t)gr * 40 + cg * 5 + j] = dv * acc[i][j];
        }
    }
}

// ---------------- Aggregation (pull-CSR), 128 features, 1 warp / node -------
// Inputs dinv-premultiplied; inner loop = gather + packed f32x2 adds.
__global__ void __launch_bounds__(256) k_agg128(int inSel, int outSel,
                                                const float* __restrict__ bias, int relu, int n) {
    const float* __restrict__ t = (inSel == 0) ? g_h0 : g_h1;
    float* o = (outSel == 0) ? g_h0 : g_h1;
    int warp = (blockIdx.x * 256 + threadIdx.x) >> 5;
    int lane = threadIdx.x & 31;
    if (warp >= n) return;
    int v = warp;
    F4U2 a0;
    a0.f = *(const float4*)(t + (size_t)v * 128 + lane * 4);   // self loop (z'[v])
    unsigned long long acc0 = a0.u[0], acc1 = a0.u[1];
    int rb = g_row[v], re = g_row[v + 1];
    for (int s0 = rb; s0 < re; s0 += 32) {
        int idx = s0 + lane;
        int u = 0;
        if (idx < re) u = g_col[idx];
        int cnt = min(32, re - s0);
        int j = 0;
        for (; j + 8 <= cnt; j += 8) {
            int uu[8]; F4U2 rr[8];
            #pragma unroll
            for (int q = 0; q < 8; q++)
                uu[q] = __shfl_sync(0xffffffffu, u, j + q);
            #pragma unroll
            for (int q = 0; q < 8; q++)
                rr[q].f = *(const float4*)(t + (size_t)uu[q] * 128 + lane * 4);
            #pragma unroll
            for (int q = 0; q < 8; q++) {
                ADD2(acc0, acc0, rr[q].u[0]);
                ADD2(acc1, acc1, rr[q].u[1]);
            }
        }
        for (; j < cnt; j++) {
            int uj = __shfl_sync(0xffffffffu, u, j);
            F4U2 r;
            r.f = *(const float4*)(t + (size_t)uj * 128 + lane * 4);
            ADD2(acc0, acc0, r.u[0]);
            ADD2(acc1, acc1, r.u[1]);
        }
    }
    float dv = g_dinv[v];
    float4 bv = *(const float4*)(bias + lane * 4);
    U64F2 c0, c1;
    c0.u = acc0; c1.u = acc1;
    float4 out;
    out.x = fmaf(dv, c0.f.x, bv.x);
    out.y = fmaf(dv, c0.f.y, bv.y);
    out.z = fmaf(dv, c1.f.x, bv.z);
    out.w = fmaf(dv, c1.f.y, bv.w);
    if (relu) {
        out.x = fmaxf(out.x, 0.f); out.y = fmaxf(out.y, 0.f);
        out.z = fmaxf(out.z, 0.f); out.w = fmaxf(out.w, 0.f);
    }
    *(float4*)(o + (size_t)v * 128 + lane * 4) = out;
}

// ---------------- Aggregation, 40 features (in g_h2, out ext) ---------------
__global__ void __launch_bounds__(256) k_agg40(float* __restrict__ O,
                                               const float* __restrict__ bias, int n) {
    int warp = (blockIdx.x * 256 + threadIdx.x) >> 5;
    int lane = threadIdx.x & 31;
    if (warp >= n) return;
    int v = warp;
    bool act = lane < 10;
    unsigned long long acc0 = 0ull, acc1 = 0ull;
    if (act) {
        F4U2 a0;
        a0.f = *(const float4*)(g_h2 + (size_t)v * 40 + lane * 4);
        acc0 = a0.u[0]; acc1 = a0.u[1];
    }
    int rb = g_row[v], re = g_row[v + 1];
    for (int s0 = rb; s0 < re; s0 += 32) {
        int idx = s0 + lane;
        int u = 0;
        if (idx < re) u = g_col[idx];
        int cnt = min(32, re - s0);
        int j = 0;
        for (; j + 4 <= cnt; j += 4) {
            int uu[4];
            #pragma unroll
            for (int q = 0; q < 4; q++)
                uu[q] = __shfl_sync(0xffffffffu, u, j + q);
            if (act) {
                F4U2 rr[4];
                #pragma unroll
                for (int q = 0; q < 4; q++)
                    rr[q].f = *(const float4*)(g_h2 + (size_t)uu[q] * 40 + lane * 4);
                #pragma unroll
                for (int q = 0; q < 4; q++) {
                    ADD2(acc0, acc0, rr[q].u[0]);
                    ADD2(acc1, acc1, rr[q].u[1]);
                }
            }
        }
        for (; j < cnt; j++) {
            int uj = __shfl_sync(0xffffffffu, u, j);
            if (act) {
                F4U2 r;
                r.f = *(const float4*)(g_h2 + (size_t)uj * 40 + lane * 4);
                ADD2(acc0, acc0, r.u[0]);
                ADD2(acc1, acc1, r.u[1]);
            }
        }
    }
    if (act) {
        float dv = g_dinv[v];
        float4 bv = *(const float4*)(bias + lane * 4);
        U64F2 c0, c1;
        c0.u = acc0; c1.u = acc1;
        float4 out;
        out.x = fmaf(dv, c0.f.x, bv.x);
        out.y = fmaf(dv, c0.f.y, bv.y);
        out.z = fmaf(dv, c1.f.x, bv.z);
        out.w = fmaf(dv, c1.f.y, bv.w);
        *(float4*)(O + (size_t)v * 40 + lane * 4) = out;
    }
}

// ---------------- launch -----------------------------------------------------
extern "C" void kernel_launch(void* const* d_in, const int* in_sizes, int n_in,
                              void* d_out, int out_size) {
    const float* x  = (const float*)d_in[0];
    const int*   ei = (const int*)d_in[1];
    const float* W0 = (const float*)d_in[2];
    const float* b0 = (const float*)d_in[3];
    const float* W1 = (const float*)d_in[4];
    const float* b1 = (const float*)d_in[5];
    const float* W2 = (const float*)d_in[6];
    const float* b2 = (const float*)d_in[7];
    float* out = (float*)d_out;

    int N = in_sizes[0] / 128;
    int E = in_sizes[1] / 2;
    const int* src = ei;
    const int* dst = ei + E;

    static bool inited = false;
    if (!inited) {
        inited = true;
        cudaFuncSetAttribute(k_gemm128, cudaFuncAttributeMaxDynamicSharedMemorySize, GSM_TOTAL);
    }

    int gb64 = (N + 63) / 64;
    int gb  = (N + 127) / 128;
    int ab  = (N + 7) / 8;
    int nb  = (N + SCAN_CH - 1) / SCAN_CH;

    // CSR: g_cnt is zero on entry (module init + re-zeroed by k_scan23 each call).
    // gemm epilogues read g_dinv, so gemm0 must follow k_scan23 (it does).
    k_count  <<<(E + 255) / 256, 256>>>(dst, E);            // #1
    k_scan1  <<<nb, SCAN_CH>>>(N);                          // #2
    k_scan23 <<<(N + 255) / 256, 256>>>(N, E, nb);          // #3
    k_gemm128<<<gb64, 128, GSM_TOTAL>>>(x, -1, W0, 0, N);   // #4 (profiled slot)
    k_scatter<<<(E + 255) / 256, 256>>>(src, dst, E);       // #5

    // layer 0: agg(h0) + b0, relu -> h1
    k_agg128 <<<ab, 256>>>(0, 1, b0, 1, N);
    // layer 1: h1 @ W1 -> h0 (dinv-scaled) ; agg(h0) + b1, relu -> h1
    k_gemm128<<<gb64, 128, GSM_TOTAL>>>(nullptr, 1, W1, 0, N);
    k_agg128 <<<ab, 256>>>(0, 1, b1, 1, N);
    // layer 2: h1 @ W2 -> h2 (dinv-scaled) ; agg(h2) + b2 -> out
    k_gemm40 <<<gb, 128>>>(W2, N);
    k_agg40  <<<ab, 256>>>(out, b2, N);
}